// round 10
// baseline (speedup 1.0000x reference)
#include <cuda_runtime.h>
#include <cuda_fp16.h>
#include <cstdint>

#define SEQ     2048
#define HIDDEN  2048
#define HEADS   32
#define GROUPS  8
#define HEAD_D  64
#define KV_DIM  512
#define QPG     4

__device__ __half g_xh[SEQ * HIDDEN];
__device__ __half g_Wqh[HIDDEN * HIDDEN];
__device__ __half g_Wkh[HIDDEN * KV_DIM];
__device__ __half g_Wvh[HIDDEN * KV_DIM];
__device__ __half g_Woh[HIDDEN * HIDDEN];
__device__ float  g_bqs[HIDDEN];
__device__ __half g_Qh[SEQ * HIDDEN];
__device__ __half g_Kh[SEQ * KV_DIM];
__device__ __half g_Vh[SEQ * KV_DIM];
__device__ __half g_Ah[SEQ * HIDDEN];

__device__ __forceinline__ uint32_t packh2(float lo, float hi) {
    __half2 h = __floats2half2_rn(lo, hi);
    return *(uint32_t*)&h;
}
__device__ __forceinline__ void mma_f16(float* c, const uint32_t* a, const uint32_t* b) {
    asm volatile(
        "mma.sync.aligned.m16n8k16.row.col.f32.f16.f16.f32 "
        "{%0,%1,%2,%3}, {%4,%5,%6,%7}, {%8,%9}, {%0,%1,%2,%3};\n"
        : "+f"(c[0]), "+f"(c[1]), "+f"(c[2]), "+f"(c[3])
        : "r"(a[0]), "r"(a[1]), "r"(a[2]), "r"(a[3]), "r"(b[0]), "r"(b[1]));
}
__device__ __forceinline__ void ldsm4(uint32_t& r0, uint32_t& r1, uint32_t& r2, uint32_t& r3, uint32_t a) {
    asm volatile("ldmatrix.sync.aligned.m8n8.x4.shared.b16 {%0,%1,%2,%3}, [%4];"
                 : "=r"(r0), "=r"(r1), "=r"(r2), "=r"(r3) : "r"(a));
}
__device__ __forceinline__ void ldsm4t(uint32_t& r0, uint32_t& r1, uint32_t& r2, uint32_t& r3, uint32_t a) {
    asm volatile("ldmatrix.sync.aligned.m8n8.x4.trans.shared.b16 {%0,%1,%2,%3}, [%4];"
                 : "=r"(r0), "=r"(r1), "=r"(r2), "=r"(r3) : "r"(a));
}
__device__ __forceinline__ void cpa16(uint32_t dst, const void* src) {
    asm volatile("cp.async.cg.shared.global [%0], [%1], 16;" :: "r"(dst), "l"(src));
}
__device__ __forceinline__ void cpcommit() { asm volatile("cp.async.commit_group;" ::: "memory"); }
template <int N> __device__ __forceinline__ void cpwait() {
    asm volatile("cp.async.wait_group %0;" :: "n"(N) : "memory");
}

// ---------------- fused precast: x, Wq*1/8, Wk, Wv, Wo, bq*1/8 in ONE launch
__device__ __forceinline__ void cast8(const float* __restrict__ s, __half* __restrict__ d,
                                      int i, float sc) {
    float4 a = *(const float4*)&s[i], b = *(const float4*)&s[i + 4];
    *(uint4*)&d[i] = make_uint4(packh2(a.x * sc, a.y * sc), packh2(a.z * sc, a.w * sc),
                                packh2(b.x * sc, b.y * sc), packh2(b.z * sc, b.w * sc));
}
__global__ __launch_bounds__(256) void cvt_all_kernel(
    const float* __restrict__ x,  const float* __restrict__ Wq,
    const float* __restrict__ Wk, const float* __restrict__ Wv,
    const float* __restrict__ Wo, const float* __restrict__ bq)
{
    int c = blockIdx.x * 256 + threadIdx.x;
    if (c < 524288)        cast8(x,  g_xh,  c * 8, 1.f);
    else if (c < 1048576)  cast8(Wq, g_Wqh, (c - 524288) * 8, 0.125f);
    else if (c < 1179648)  cast8(Wk, g_Wkh, (c - 1048576) * 8, 1.f);
    else if (c < 1310720)  cast8(Wv, g_Wvh, (c - 1179648) * 8, 1.f);
    else if (c < 1835008)  cast8(Wo, g_Woh, (c - 1310720) * 8, 1.f);
    else {
        int i = (c - 1835008) * 8;
        float4 a = *(const float4*)&bq[i], b = *(const float4*)&bq[i + 4];
        *(float4*)&g_bqs[i]     = make_float4(a.x * .125f, a.y * .125f, a.z * .125f, a.w * .125f);
        *(float4*)&g_bqs[i + 4] = make_float4(b.x * .125f, b.y * .125f, b.z * .125f, b.w * .125f);
    }
}

// ---------------------------------------------------------------------------
// fp16 HMMA GEMM: 128x256 block tile, 8 warps of 64x64, BK=32, 3-stage cp.async.
// Stage: A [128][40] + B [32][264] halves. Row strides 20/132 words (4 mod 8,
// odd multiple of 4) -> ldmatrix conflict-free.
// ---------------------------------------------------------------------------
#define STG     3
#define STG_B   27136                 // (5120 + 8448) halves * 2 bytes
#define GSMEM   (STG * STG_B)         // 81408 bytes

__device__ void hgemm16(const __half* __restrict__ A, const __half* __restrict__ B,
                        const float* __restrict__ bias, void* __restrict__ Cv,
                        int N, int K, int rb, int cb, int outHalf)
{
    extern __shared__ __half hs[];
    const int tid = threadIdx.x, warp = tid >> 5, lane = tid & 31;
    const int gid = lane >> 2, tg = lane & 3;
    const int mBase = (warp & 1) * 64, nBase = (warp >> 1) * 64;
    const uint32_t sbase = (uint32_t)__cvta_generic_to_shared(hs);

    const __half* Ab = A + (size_t)rb * 128 * K;
    const __half* Bb = B + (size_t)cb * 256;

    float acc[4][8][4];
#pragma unroll
    for (int i = 0; i < 4; i++)
#pragma unroll
        for (int j = 0; j < 8; j++)
#pragma unroll
            for (int r = 0; r < 4; r++) acc[i][j][r] = 0.f;

    const int T = K / 32;

    auto issue = [&](int t, int st) {
        uint32_t as = sbase + st * STG_B;
        uint32_t bs = as + 5120 * 2;
#pragma unroll
        for (int p = 0; p < 2; p++) {   // A: 512 chunks of 8 halves
            int s = tid + p * 256, row = s >> 2, c8 = (s & 3) * 8;
            cpa16(as + (row * 40 + c8) * 2, Ab + (size_t)row * K + t * 32 + c8);
        }
#pragma unroll
        for (int p = 0; p < 4; p++) {   // B: 1024 chunks
            int s = tid + p * 256, row = s >> 5, c8 = (s & 31) * 8;
            cpa16(bs + (row * 264 + c8) * 2, Bb + (size_t)(t * 32 + row) * N + c8);
        }
    };

#pragma unroll
    for (int s = 0; s < STG; s++) { issue(s, s); cpcommit(); }

    for (int t = 0; t < T; t++) {
        cpwait<STG - 1>();
        __syncthreads();
        const int st = t % STG;
        const uint32_t as = sbase + st * STG_B;
        const uint32_t bs = as + 5120 * 2;
#pragma unroll
        for (int k0 = 0; k0 < 32; k0 += 16) {
            uint32_t af[4][4], bf[8][2];
#pragma unroll
            for (int mt = 0; mt < 4; mt++)
                ldsm4(af[mt][0], af[mt][1], af[mt][2], af[mt][3],
                      as + ((mBase + mt * 16 + (lane & 15)) * 40 + k0 + (lane >> 4) * 8) * 2);
#pragma unroll
            for (int np = 0; np < 4; np++)
                ldsm4t(bf[2 * np][0], bf[2 * np][1], bf[2 * np + 1][0], bf[2 * np + 1][1],
                       bs + ((k0 + (lane & 15)) * 264 + nBase + np * 16 + (lane >> 4) * 8) * 2);
#pragma unroll
            for (int mt = 0; mt < 4; mt++)
#pragma unroll
                for (int nt = 0; nt < 8; nt++)
                    mma_f16(acc[mt][nt], af[mt], bf[nt]);
        }
        __syncthreads();
        if (t + STG < T) issue(t + STG, st);
        cpcommit();
    }

#pragma unroll
    for (int mt = 0; mt < 4; mt++) {
#pragma unroll
        for (int nt = 0; nt < 8; nt++) {
            int row = rb * 128 + mBase + mt * 16 + gid;
            int col = cb * 256 + nBase + nt * 8 + tg * 2;
            float bx = bias[col], by = bias[col + 1];
            if (outHalf) {
                __half* C = (__half*)Cv;
                *(uint32_t*)&C[(size_t)row * N + col]       = packh2(acc[mt][nt][0] + bx, acc[mt][nt][1] + by);
                *(uint32_t*)&C[(size_t)(row + 8) * N + col] = packh2(acc[mt][nt][2] + bx, acc[mt][nt][3] + by);
            } else {
                float* C = (float*)Cv;
                *(float2*)&C[(size_t)row * N + col]       = make_float2(acc[mt][nt][0] + bx, acc[mt][nt][1] + by);
                *(float2*)&C[(size_t)(row + 8) * N + col] = make_float2(acc[mt][nt][2] + bx, acc[mt][nt][3] + by);
            }
        }
    }
}

__global__ __launch_bounds__(256) void h_qkv_kernel(
    const float* __restrict__ bk, const float* __restrict__ bv)
{
    int bx = blockIdx.x;
    if (bx < 8)       hgemm16(g_xh, g_Wqh, g_bqs, g_Qh, HIDDEN, HIDDEN, blockIdx.y, bx, 1);
    else if (bx < 10) hgemm16(g_xh, g_Wkh, bk, g_Kh, KV_DIM, HIDDEN, blockIdx.y, bx - 8, 1);
    else              hgemm16(g_xh, g_Wvh, bv, g_Vh, KV_DIM, HIDDEN, blockIdx.y, bx - 10, 1);
}
__global__ __launch_bounds__(256) void h_out_kernel(const float* __restrict__ bo, float* __restrict__ out)
{
    hgemm16(g_Ah, g_Woh, bo, out, HIDDEN, HIDDEN, blockIdx.y, blockIdx.x, 0);
}

// ---------------------------------------------------------------------------
// fp16 flash attention, double-buffered cp.async K/V tiles.
// grid=(SEQ/128, HEADS), block=128 (4 warps x 32 q-rows).
// ---------------------------------------------------------------------------
__global__ __launch_bounds__(128) void flash_h_kernel()
{
    __shared__ __half Ks[2][64][72];
    __shared__ __half Vs[2][64][72];

    const int qblk = gridDim.x - 1 - blockIdx.x;
    const int h = blockIdx.y, g = h / QPG, q0 = qblk * 128;
    const int tid = threadIdx.x, warp = tid >> 5, lane = tid & 31;
    const int gid = lane >> 2, tg = lane & 3;

    uint32_t qa[2][4][4];
#pragma unroll
    for (int mt = 0; mt < 2; mt++) {
        const __half* QbA = g_Qh + (size_t)(q0 + warp * 32 + mt * 16 + gid) * HIDDEN + h * HEAD_D;
        const __half* QbB = QbA + 8 * HIDDEN;
#pragma unroll
        for (int ks = 0; ks < 4; ks++) {
            int c = ks * 16 + 2 * tg;
            qa[mt][ks][0] = *(const uint32_t*)&QbA[c];
            qa[mt][ks][1] = *(const uint32_t*)&QbB[c];
            qa[mt][ks][2] = *(const uint32_t*)&QbA[c + 8];
            qa[mt][ks][3] = *(const uint32_t*)&QbB[c + 8];
        }
    }

    float accO[2][8][4];
#pragma unroll
    for (int mt = 0; mt < 2; mt++)
#pragma unroll
        for (int nt = 0; nt < 8; nt++)
#pragma unroll
            for (int r = 0; r < 4; r++) accO[mt][nt][r] = 0.f;
    float mA[2] = {-1e30f, -1e30f}, mB[2] = {-1e30f, -1e30f};
    float lA[2] = {0.f, 0.f}, lB[2] = {0.f, 0.f};

    const int ntiles = 2 * qblk + 2;
    const int wmin = q0 + warp * 32, wmax = wmin + 31;

    auto issueKV = [&](int t) {
        int b = t & 1, j0 = t * 64;
#pragma unroll
        for (int i = 0; i < 4; i++) {
            int s = tid + i * 128, row = s >> 3, c8 = (s & 7) * 8;
            cpa16((uint32_t)__cvta_generic_to_shared(&Ks[b][row][c8]),
                  g_Kh + (size_t)(j0 + row) * KV_DIM + g * HEAD_D + c8);
        }
#pragma unroll
        for (int i = 0; i < 4; i++) {
            int s = tid + i * 128, row = s >> 3, c8 = (s & 7) * 8;
            cpa16((uint32_t)__cvta_generic_to_shared(&Vs[b][row][c8]),
                  g_Vh + (size_t)(j0 + row) * KV_DIM + g * HEAD_D + c8);
        }
    };

    issueKV(0);
    cpcommit();

    for (int t = 0; t < ntiles; t++) {
        const int j0 = t * 64, buf = t & 1;
        __syncthreads();                 // all warps done with buf (t-1)&1
        if (t + 1 < ntiles) { issueKV(t + 1); cpcommit(); cpwait<1>(); }
        else                { cpwait<0>(); }
        __syncthreads();
        if (j0 > wmax) continue;

        float accS[2][8][4];
#pragma unroll
        for (int mt = 0; mt < 2; mt++)
#pragma unroll
            for (int nt = 0; nt < 8; nt++)
#pragma unroll
                for (int r = 0; r < 4; r++) accS[mt][nt][r] = 0.f;

#pragma unroll
        for (int ks = 0; ks < 4; ks++) {
#pragma unroll
            for (int np = 0; np < 4; np++) {
                uint32_t r0, r1, r2, r3;
                ldsm4(r0, r1, r2, r3,
                      (uint32_t)__cvta_generic_to_shared(
                          &Ks[buf][np * 16 + (lane & 15)][ks * 16 + (lane >> 4) * 8]));
                uint32_t b0[2] = {r0, r2}, b1[2] = {r1, r3};
                mma_f16(accS[0][2 * np],     qa[0][ks], b0);
                mma_f16(accS[1][2 * np],     qa[1][ks], b0);
                mma_f16(accS[0][2 * np + 1], qa[0][ks], b1);
                mma_f16(accS[1][2 * np + 1], qa[1][ks], b1);
            }
        }

        if (j0 + 63 > wmin) {
#pragma unroll
            for (int mt = 0; mt < 2; mt++) {
                int rA = wmin + mt * 16 + gid;
#pragma unroll
                for (int nt = 0; nt < 8; nt++) {
                    int k0 = j0 + nt * 8 + 2 * tg;
                    if (k0     > rA)     accS[mt][nt][0] = -1e30f;
                    if (k0 + 1 > rA)     accS[mt][nt][1] = -1e30f;
                    if (k0     > rA + 8) accS[mt][nt][2] = -1e30f;
                    if (k0 + 1 > rA + 8) accS[mt][nt][3] = -1e30f;
                }
            }
        }

#pragma unroll
        for (int mt = 0; mt < 2; mt++) {
            float mx0 = -1e30f, mx1 = -1e30f;
#pragma unroll
            for (int nt = 0; nt < 8; nt++) {
                mx0 = fmaxf(mx0, fmaxf(accS[mt][nt][0], accS[mt][nt][1]));
                mx1 = fmaxf(mx1, fmaxf(accS[mt][nt][2], accS[mt][nt][3]));
            }
            mx0 = fmaxf(mx0, __shfl_xor_sync(0xffffffffu, mx0, 1));
            mx0 = fmaxf(mx0, __shfl_xor_sync(0xffffffffu, mx0, 2));
            mx1 = fmaxf(mx1, __shfl_xor_sync(0xffffffffu, mx1, 1));
            mx1 = fmaxf(mx1, __shfl_xor_sync(0xffffffffu, mx1, 2));
            float mn0 = fmaxf(mA[mt], mx0), mn1 = fmaxf(mB[mt], mx1);
            float sc0 = __expf(mA[mt] - mn0), sc1 = __expf(mB[mt] - mn1);
            float s0 = 0.f, s1 = 0.f;
#pragma unroll
            for (int nt = 0; nt < 8; nt++) {
                accS[mt][nt][0] = __expf(accS[mt][nt][0] - mn0);
                accS[mt][nt][1] = __expf(accS[mt][nt][1] - mn0);
                accS[mt][nt][2] = __expf(accS[mt][nt][2] - mn1);
                accS[mt][nt][3] = __expf(accS[mt][nt][3] - mn1);
                s0 += accS[mt][nt][0] + accS[mt][nt][1];
                s1 += accS[mt][nt][2] + accS[mt][nt][3];
            }
            s0 += __shfl_xor_sync(0xffffffffu, s0, 1);
            s0 += __shfl_xor_sync(0xffffffffu, s0, 2);
            s1 += __shfl_xor_sync(0xffffffffu, s1, 1);
            s1 += __shfl_xor_sync(0xffffffffu, s1, 2);
            lA[mt] = lA[mt] * sc0 + s0;
            lB[mt] = lB[mt] * sc1 + s1;
            mA[mt] = mn0; mB[mt] = mn1;
#pragma unroll
            for (int nt = 0; nt < 8; nt++) {
                accO[mt][nt][0] *= sc0; accO[mt][nt][1] *= sc0;
                accO[mt][nt][2] *= sc1; accO[mt][nt][3] *= sc1;
            }
        }

#pragma unroll
        for (int ks = 0; ks < 4; ks++) {
            uint32_t pa[2][4];
#pragma unroll
            for (int mt = 0; mt < 2; mt++) {
                pa[mt][0] = packh2(accS[mt][2 * ks][0],     accS[mt][2 * ks][1]);
                pa[mt][1] = packh2(accS[mt][2 * ks][2],     accS[mt][2 * ks][3]);
                pa[mt][2] = packh2(accS[mt][2 * ks + 1][0], accS[mt][2 * ks + 1][1]);
                pa[mt][3] = packh2(accS[mt][2 * ks + 1][2], accS[mt][2 * ks + 1][3]);
            }
#pragma unroll
            for (int np = 0; np < 4; np++) {
                uint32_t r0, r1, r2, r3;
                ldsm4t(r0, r1, r2, r3,
                       (uint32_t)__cvta_generic_to_shared(
                           &Vs[buf][ks * 16 + (lane & 15)][np * 16 + (lane >> 4) * 8]));
                uint32_t b0[2] = {r0, r1}, b1[2] = {r2, r3};
                mma_f16(accO[0][2 * np],     pa[0], b0);
                mma_f16(accO[1][2 * np],     pa[1], b0);
                mma_f16(accO[0][2 * np + 1], pa[0], b1);
                mma_f16(accO[1][2 * np + 1], pa[1], b1);
            }
        }
    }

#pragma unroll
    for (int mt = 0; mt < 2; mt++) {
        float inv0 = 1.f / lA[mt], inv1 = 1.f / lB[mt];
        __half* Ob = g_Ah + (size_t)(q0 + warp * 32 + mt * 16 + gid) * HIDDEN + h * HEAD_D;
#pragma unroll
        for (int nt = 0; nt < 8; nt++) {
            int c = nt * 8 + 2 * tg;
            *(uint32_t*)&Ob[c]              = packh2(accO[mt][nt][0] * inv0, accO[mt][nt][1] * inv0);
            *(uint32_t*)&Ob[8 * HIDDEN + c] = packh2(accO[mt][nt][2] * inv1, accO[mt][nt][3] * inv1);
        }
    }
}

// ---------------------------------------------------------------------------
extern "C" void kernel_launch(void* const* d_in, const int* in_sizes, int n_in,
                              void* d_out, int out_size)
{
    const float* x  = (const float*)d_in[0];
    const float* Wq = (const float*)d_in[2];
    const float* bq = (const float*)d_in[3];
    const float* Wk = (const float*)d_in[4];
    const float* bk = (const float*)d_in[5];
    const float* Wv = (const float*)d_in[6];
    const float* bv = (const float*)d_in[7];
    const float* Wo = (const float*)d_in[8];
    const float* bo = (const float*)d_in[9];
    float* out = (float*)d_out;

    static int attr_done = 0;
    if (!attr_done) {
        cudaFuncSetAttribute(h_qkv_kernel, cudaFuncAttributeMaxDynamicSharedMemorySize, GSMEM);
        cudaFuncSetAttribute(h_out_kernel, cudaFuncAttributeMaxDynamicSharedMemorySize, GSMEM);
        attr_done = 1;
    }

    cvt_all_kernel<<<7169, 256>>>(x, Wq, Wk, Wv, Wo, bq);
    h_qkv_kernel<<<dim3(12, SEQ / 128), 256, GSMEM>>>(bk, bv);
    flash_h_kernel<<<dim3(SEQ / 128, HEADS), dim3(128)>>>();
    h_out_kernel<<<dim3(HIDDEN / 256, SEQ / 128), 256, GSMEM>>>(bo, out);
}

// round 12
// speedup vs baseline: 1.1606x; 1.1606x over previous
#include <cuda_runtime.h>
#include <cuda_fp16.h>
#include <cstdint>

#define SEQ     2048
#define HIDDEN  2048
#define HEADS   32
#define GROUPS  8
#define HEAD_D  64
#define KV_DIM  512
#define QPG     4

__device__ __half g_xh[SEQ * HIDDEN];
__device__ __half g_Wqh[HIDDEN * HIDDEN];
__device__ __half g_Wkh[HIDDEN * KV_DIM];
__device__ __half g_Wvh[HIDDEN * KV_DIM];
__device__ __half g_Woh[HIDDEN * HIDDEN];
__device__ float  g_bqs[HIDDEN];
__device__ __half g_Qh[SEQ * HIDDEN];
__device__ __half g_Kh[SEQ * KV_DIM];
__device__ __half g_Vh[SEQ * KV_DIM];
__device__ __half g_Ah[SEQ * HIDDEN];

__device__ __forceinline__ uint32_t packh2(float lo, float hi) {
    __half2 h = __floats2half2_rn(lo, hi);
    return *(uint32_t*)&h;
}
__device__ __forceinline__ void mma_f16(float* c, const uint32_t* a, const uint32_t* b) {
    asm volatile(
        "mma.sync.aligned.m16n8k16.row.col.f32.f16.f16.f32 "
        "{%0,%1,%2,%3}, {%4,%5,%6,%7}, {%8,%9}, {%0,%1,%2,%3};\n"
        : "+f"(c[0]), "+f"(c[1]), "+f"(c[2]), "+f"(c[3])
        : "r"(a[0]), "r"(a[1]), "r"(a[2]), "r"(a[3]), "r"(b[0]), "r"(b[1]));
}
__device__ __forceinline__ void ldsm4(uint32_t& r0, uint32_t& r1, uint32_t& r2, uint32_t& r3, uint32_t a) {
    asm volatile("ldmatrix.sync.aligned.m8n8.x4.shared.b16 {%0,%1,%2,%3}, [%4];"
                 : "=r"(r0), "=r"(r1), "=r"(r2), "=r"(r3) : "r"(a));
}
__device__ __forceinline__ void ldsm4t(uint32_t& r0, uint32_t& r1, uint32_t& r2, uint32_t& r3, uint32_t a) {
    asm volatile("ldmatrix.sync.aligned.m8n8.x4.trans.shared.b16 {%0,%1,%2,%3}, [%4];"
                 : "=r"(r0), "=r"(r1), "=r"(r2), "=r"(r3) : "r"(a));
}
__device__ __forceinline__ void cpa16(uint32_t dst, const void* src) {
    asm volatile("cp.async.cg.shared.global [%0], [%1], 16;" :: "r"(dst), "l"(src));
}
__device__ __forceinline__ void cpcommit() { asm volatile("cp.async.commit_group;" ::: "memory"); }
template <int N> __device__ __forceinline__ void cpwait() {
    asm volatile("cp.async.wait_group %0;" :: "n"(N) : "memory");
}
__device__ __forceinline__ uint32_t h2exp2(uint32_t u) {
    uint32_t r;
    asm("ex2.approx.f16x2 %0, %1;" : "=r"(r) : "r"(u));
    return r;
}

// ---------------- fused precast: x, Wq*1/8, Wk, Wv, Wo, bq*1/8 (one launch)
__device__ __forceinline__ void cast8(const float* __restrict__ s, __half* __restrict__ d,
                                      int i, float sc) {
    float4 a = *(const float4*)&s[i], b = *(const float4*)&s[i + 4];
    *(uint4*)&d[i] = make_uint4(packh2(a.x * sc, a.y * sc), packh2(a.z * sc, a.w * sc),
                                packh2(b.x * sc, b.y * sc), packh2(b.z * sc, b.w * sc));
}
__global__ __launch_bounds__(256) void cvt_all_kernel(
    const float* __restrict__ x,  const float* __restrict__ Wq,
    const float* __restrict__ Wk, const float* __restrict__ Wv,
    const float* __restrict__ Wo, const float* __restrict__ bq)
{
    int c = blockIdx.x * 256 + threadIdx.x;
    if (c < 524288)        cast8(x,  g_xh,  c * 8, 1.f);
    else if (c < 1048576)  cast8(Wq, g_Wqh, (c - 524288) * 8, 0.125f);
    else if (c < 1179648)  cast8(Wk, g_Wkh, (c - 1048576) * 8, 1.f);
    else if (c < 1310720)  cast8(Wv, g_Wvh, (c - 1179648) * 8, 1.f);
    else if (c < 1835008)  cast8(Wo, g_Woh, (c - 1310720) * 8, 1.f);
    else {
        int i = (c - 1835008) * 8;
        float4 a = *(const float4*)&bq[i], b = *(const float4*)&bq[i + 4];
        *(float4*)&g_bqs[i]     = make_float4(a.x * .125f, a.y * .125f, a.z * .125f, a.w * .125f);
        *(float4*)&g_bqs[i + 4] = make_float4(b.x * .125f, b.y * .125f, b.z * .125f, b.w * .125f);
    }
}

// ---------------------------------------------------------------------------
// fp16 HMMA GEMM: 128x128 block tile, 8 warps of 64x32, BK=32, 4-stage
// cp.async, cutlass-style multistage (one sync/iter, issue before compute),
// 2 CTAs/SM. Stage: A [128][40] + B [32][136] halves.
// ---------------------------------------------------------------------------
#define STG     4
#define STG_B   18944                 // (5120 + 4352) halves * 2 bytes
#define GSMEM   (STG * STG_B)        // 75776 bytes

__device__ void hgemm16(const __half* __restrict__ A, const __half* __restrict__ B,
                        const float* __restrict__ bias, void* __restrict__ Cv,
                        int N, int K, int rb, int cb, int outHalf)
{
    extern __shared__ __half hs[];
    const int tid = threadIdx.x, warp = tid >> 5, lane = tid & 31;
    const int gid = lane >> 2, tg = lane & 3;
    const int mBase = (warp & 1) * 64, nBase = (warp >> 1) * 32;
    const uint32_t sbase = (uint32_t)__cvta_generic_to_shared(hs);

    const __half* Ab = A + (size_t)rb * 128 * K;
    const __half* Bb = B + (size_t)cb * 128;

    float acc[4][4][4];
#pragma unroll
    for (int i = 0; i < 4; i++)
#pragma unroll
        for (int j = 0; j < 4; j++)
#pragma unroll
            for (int r = 0; r < 4; r++) acc[i][j][r] = 0.f;

    const int T = K / 32;

    auto issue = [&](int t) {
        uint32_t as = sbase + (t % STG) * STG_B;
        uint32_t bs = as + 5120 * 2;
#pragma unroll
        for (int p = 0; p < 2; p++) {   // A: 512 chunks of 8 halves
            int s = tid + p * 256, row = s >> 2, c8 = (s & 3) * 8;
            cpa16(as + (row * 40 + c8) * 2, Ab + (size_t)row * K + t * 32 + c8);
        }
#pragma unroll
        for (int p = 0; p < 2; p++) {   // B: 512 chunks
            int s = tid + p * 256, row = s >> 4, c8 = (s & 15) * 8;
            cpa16(bs + (row * 136 + c8) * 2, Bb + (size_t)(t * 32 + row) * N + c8);
        }
    };

#pragma unroll
    for (int s = 0; s < STG - 1; s++) { issue(s); cpcommit(); }

    for (int t = 0; t < T; t++) {
        cpwait<STG - 2>();           // stage t arrived
        __syncthreads();             // all warps past compute(t-1); data visible
        if (t + STG - 1 < T) issue(t + STG - 1);   // buffer (t-1)%STG, now free
        cpcommit();
        const uint32_t as = sbase + (t % STG) * STG_B;
        const uint32_t bs = as + 5120 * 2;
#pragma unroll
        for (int k0 = 0; k0 < 32; k0 += 16) {
            uint32_t af[4][4], bf[4][2];
#pragma unroll
            for (int mt = 0; mt < 4; mt++)
                ldsm4(af[mt][0], af[mt][1], af[mt][2], af[mt][3],
                      as + ((mBase + mt * 16 + (lane & 15)) * 40 + k0 + (lane >> 4) * 8) * 2);
#pragma unroll
            for (int np = 0; np < 2; np++)
                ldsm4t(bf[2 * np][0], bf[2 * np][1], bf[2 * np + 1][0], bf[2 * np + 1][1],
                       bs + ((k0 + (lane & 15)) * 136 + nBase + np * 16 + (lane >> 4) * 8) * 2);
#pragma unroll
            for (int mt = 0; mt < 4; mt++)
#pragma unroll
                for (int nt = 0; nt < 4; nt++)
                    mma_f16(acc[mt][nt], af[mt], bf[nt]);
        }
    }

#pragma unroll
    for (int mt = 0; mt < 4; mt++) {
#pragma unroll
        for (int nt = 0; nt < 4; nt++) {
            int row = rb * 128 + mBase + mt * 16 + gid;
            int col = cb * 128 + nBase + nt * 8 + tg * 2;
            float bx = bias[col], by = bias[col + 1];
            if (outHalf) {
                __half* C = (__half*)Cv;
                *(uint32_t*)&C[(size_t)row * N + col]       = packh2(acc[mt][nt][0] + bx, acc[mt][nt][1] + by);
                *(uint32_t*)&C[(size_t)(row + 8) * N + col] = packh2(acc[mt][nt][2] + bx, acc[mt][nt][3] + by);
            } else {
                float* C = (float*)Cv;
                *(float2*)&C[(size_t)row * N + col]       = make_float2(acc[mt][nt][0] + bx, acc[mt][nt][1] + by);
                *(float2*)&C[(size_t)(row + 8) * N + col] = make_float2(acc[mt][nt][2] + bx, acc[mt][nt][3] + by);
            }
        }
    }
}

__global__ __launch_bounds__(256, 2) void h_qkv_kernel(
    const float* __restrict__ bk, const float* __restrict__ bv)
{
    int bx = blockIdx.x;
    if (bx < 16)      hgemm16(g_xh, g_Wqh, g_bqs, g_Qh, HIDDEN, HIDDEN, blockIdx.y, bx, 1);
    else if (bx < 20) hgemm16(g_xh, g_Wkh, bk, g_Kh, KV_DIM, HIDDEN, blockIdx.y, bx - 16, 1);
    else              hgemm16(g_xh, g_Wvh, bv, g_Vh, KV_DIM, HIDDEN, blockIdx.y, bx - 20, 1);
}
__global__ __launch_bounds__(256, 2) void h_out_kernel(const float* __restrict__ bo, float* __restrict__ out)
{
    hgemm16(g_Ah, g_Woh, bo, out, HIDDEN, HIDDEN, blockIdx.y, blockIdx.x, 0);
}

// ---------------------------------------------------------------------------
// fp16 flash attention, double-buffered cp.async K/V, f16x2 exp2 softmax.
// grid=(SEQ/128, HEADS), block=128 (4 warps x 32 q-rows).
// ---------------------------------------------------------------------------
__global__ __launch_bounds__(128) void flash_h_kernel()
{
    __shared__ __half Ks[2][64][72];
    __shared__ __half Vs[2][64][72];

    const int qblk = gridDim.x - 1 - blockIdx.x;
    const int h = blockIdx.y, g = h / QPG, q0 = qblk * 128;
    const int tid = threadIdx.x, warp = tid >> 5, lane = tid & 31;
    const int gid = lane >> 2, tg = lane & 3;
    const float L2E = 1.44269504f;

    uint32_t qa[2][4][4];
#pragma unroll
    for (int mt = 0; mt < 2; mt++) {
        const __half* QbA = g_Qh + (size_t)(q0 + warp * 32 + mt * 16 + gid) * HIDDEN + h * HEAD_D;
        const __half* QbB = QbA + 8 * HIDDEN;
#pragma unroll
        for (int ks = 0; ks < 4; ks++) {
            int c = ks * 16 + 2 * tg;
            qa[mt][ks][0] = *(const uint32_t*)&QbA[c];
            qa[mt][ks][1] = *(const uint32_t*)&QbB[c];
            qa[mt][ks][2] = *(const uint32_t*)&QbA[c + 8];
            qa[mt][ks][3] = *(const uint32_t*)&QbB[c + 8];
        }
    }

    float accO[2][8][4];
#pragma unroll
    for (int mt = 0; mt < 2; mt++)
#pragma unroll
        for (int nt = 0; nt < 8; nt++)
#pragma unroll
            for (int r = 0; r < 4; r++) accO[mt][nt][r] = 0.f;
    float mA[2] = {-1e30f, -1e30f}, mB[2] = {-1e30f, -1e30f};
    float lA[2] = {0.f, 0.f}, lB[2] = {0.f, 0.f};

    const int ntiles = 2 * qblk + 2;
    const int wmin = q0 + warp * 32, wmax = wmin + 31;

    auto issueKV = [&](int t) {
        int b = t & 1, j0 = t * 64;
#pragma unroll
        for (int i = 0; i < 4; i++) {
            int s = tid + i * 128, row = s >> 3, c8 = (s & 7) * 8;
            cpa16((uint32_t)__cvta_generic_to_shared(&Ks[b][row][c8]),
                  g_Kh + (size_t)(j0 + row) * KV_DIM + g * HEAD_D + c8);
        }
#pragma unroll
        for (int i = 0; i < 4; i++) {
            int s = tid + i * 128, row = s >> 3, c8 = (s & 7) * 8;
            cpa16((uint32_t)__cvta_generic_to_shared(&Vs[b][row][c8]),
                  g_Vh + (size_t)(j0 + row) * KV_DIM + g * HEAD_D + c8);
        }
    };

    issueKV(0);
    cpcommit();

    for (int t = 0; t < ntiles; t++) {
        const int j0 = t * 64, buf = t & 1;
        __syncthreads();
        if (t + 1 < ntiles) { issueKV(t + 1); cpcommit(); cpwait<1>(); }
        else                { cpwait<0>(); }
        __syncthreads();
        if (j0 > wmax) continue;

        float accS[2][8][4];
#pragma unroll
        for (int mt = 0; mt < 2; mt++)
#pragma unroll
            for (int nt = 0; nt < 8; nt++)
#pragma unroll
                for (int r = 0; r < 4; r++) accS[mt][nt][r] = 0.f;

#pragma unroll
        for (int ks = 0; ks < 4; ks++) {
#pragma unroll
            for (int np = 0; np < 4; np++) {
                uint32_t r0, r1, r2, r3;
                ldsm4(r0, r1, r2, r3,
                      (uint32_t)__cvta_generic_to_shared(
                          &Ks[buf][np * 16 + (lane & 15)][ks * 16 + (lane >> 4) * 8]));
                uint32_t b0[2] = {r0, r2}, b1[2] = {r1, r3};
                mma_f16(accS[0][2 * np],     qa[0][ks], b0);
                mma_f16(accS[1][2 * np],     qa[1][ks], b0);
                mma_f16(accS[0][2 * np + 1], qa[0][ks], b1);
                mma_f16(accS[1][2 * np + 1], qa[1][ks], b1);
            }
        }

        if (j0 + 63 > wmin) {
#pragma unroll
            for (int mt = 0; mt < 2; mt++) {
                int rA = wmin + mt * 16 + gid;
#pragma unroll
                for (int nt = 0; nt < 8; nt++) {
                    int k0 = j0 + nt * 8 + 2 * tg;
                    if (k0     > rA)     accS[mt][nt][0] = -1e30f;
                    if (k0 + 1 > rA)     accS[mt][nt][1] = -1e30f;
                    if (k0     > rA + 8) accS[mt][nt][2] = -1e30f;
                    if (k0 + 1 > rA + 8) accS[mt][nt][3] = -1e30f;
                }
            }
        }

        // softmax: p = exp2((s-mn)*log2e) on fp16x2 MUFU; masked lanes -> -inf -> 0
        uint32_t p0[2][8], p1[2][8];
#pragma unroll
        for (int mt = 0; mt < 2; mt++) {
            float mx0 = -1e30f, mx1 = -1e30f;
#pragma unroll
            for (int nt = 0; nt < 8; nt++) {
                mx0 = fmaxf(mx0, fmaxf(accS[mt][nt][0], accS[mt][nt][1]));
                mx1 = fmaxf(mx1, fmaxf(accS[mt][nt][2], accS[mt][nt][3]));
            }
            mx0 = fmaxf(mx0, __shfl_xor_sync(0xffffffffu, mx0, 1));
            mx0 = fmaxf(mx0, __shfl_xor_sync(0xffffffffu, mx0, 2));
            mx1 = fmaxf(mx1, __shfl_xor_sync(0xffffffffu, mx1, 1));
            mx1 = fmaxf(mx1, __shfl_xor_sync(0xffffffffu, mx1, 2));
            float mn0 = fmaxf(mA[mt], mx0), mn1 = fmaxf(mB[mt], mx1);
            float sc0 = __expf(mA[mt] - mn0), sc1 = __expf(mB[mt] - mn1);
            float s0 = 0.f, s1 = 0.f;
#pragma unroll
            for (int nt = 0; nt < 8; nt++) {
                uint32_t u0 = h2exp2(packh2((accS[mt][nt][0] - mn0) * L2E,
                                            (accS[mt][nt][1] - mn0) * L2E));
                uint32_t u1 = h2exp2(packh2((accS[mt][nt][2] - mn1) * L2E,
                                            (accS[mt][nt][3] - mn1) * L2E));
                p0[mt][nt] = u0;
                p1[mt][nt] = u1;
                float2 f0 = __half22float2(*(__half2*)&u0);
                float2 f1 = __half22float2(*(__half2*)&u1);
                s0 += f0.x + f0.y;
                s1 += f1.x + f1.y;
            }
            s0 += __shfl_xor_sync(0xffffffffu, s0, 1);
            s0 += __shfl_xor_sync(0xffffffffu, s0, 2);
            s1 += __shfl_xor_sync(0xffffffffu, s1, 1);
            s1 += __shfl_xor_sync(0xffffffffu, s1, 2);
            lA[mt] = lA[mt] * sc0 + s0;
            lB[mt] = lB[mt] * sc1 + s1;
            mA[mt] = mn0; mB[mt] = mn1;
#pragma unroll
            for (int nt = 0; nt < 8; nt++) {
                accO[mt][nt][0] *= sc0; accO[mt][nt][1] *= sc0;
                accO[mt][nt][2] *= sc1; accO[mt][nt][3] *= sc1;
            }
        }

        // O += P @ V ; P a-frags come straight from p0/p1
#pragma unroll
        for (int ks = 0; ks < 4; ks++) {
            uint32_t pa[2][4];
#pragma unroll
            for (int mt = 0; mt < 2; mt++) {
                pa[mt][0] = p0[mt][2 * ks];
                pa[mt][1] = p1[mt][2 * ks];
                pa[mt][2] = p0[mt][2 * ks + 1];
                pa[mt][3] = p1[mt][2 * ks + 1];
            }
#pragma unroll
            for (int np = 0; np < 4; np++) {
                uint32_t r0, r1, r2, r3;
                ldsm4t(r0, r1, r2, r3,
                       (uint32_t)__cvta_generic_to_shared(
                           &Vs[buf][ks * 16 + (lane & 15)][np * 16 + (lane >> 4) * 8]));
                uint32_t b0[2] = {r0, r1}, b1[2] = {r2, r3};
                mma_f16(accO[0][2 * np],     pa[0], b0);
                mma_f16(accO[1][2 * np],     pa[1], b0);
                mma_f16(accO[0][2 * np + 1], pa[0], b1);
                mma_f16(accO[1][2 * np + 1], pa[1], b1);
            }
        }
    }

#pragma unroll
    for (int mt = 0; mt < 2; mt++) {
        float inv0 = 1.f / lA[mt], inv1 = 1.f / lB[mt];
        __half* Ob = g_Ah + (size_t)(q0 + warp * 32 + mt * 16 + gid) * HIDDEN + h * HEAD_D;
#pragma unroll
        for (int nt = 0; nt < 8; nt++) {
            int c = nt * 8 + 2 * tg;
            *(uint32_t*)&Ob[c]              = packh2(accO[mt][nt][0] * inv0, accO[mt][nt][1] * inv0);
            *(uint32_t*)&Ob[8 * HIDDEN + c] = packh2(accO[mt][nt][2] * inv1, accO[mt][nt][3] * inv1);
        }
    }
}

// ---------------------------------------------------------------------------
extern "C" void kernel_launch(void* const* d_in, const int* in_sizes, int n_in,
                              void* d_out, int out_size)
{
    const float* x  = (const float*)d_in[0];
    const float* Wq = (const float*)d_in[2];
    const float* bq = (const float*)d_in[3];
    const float* Wk = (const float*)d_in[4];
    const float* bk = (const float*)d_in[5];
    const float* Wv = (const float*)d_in[6];
    const float* bv = (const float*)d_in[7];
    const float* Wo = (const float*)d_in[8];
    const float* bo = (const float*)d_in[9];
    float* out = (float*)d_out;

    static int attr_done = 0;
    if (!attr_done) {
        cudaFuncSetAttribute(h_qkv_kernel, cudaFuncAttributeMaxDynamicSharedMemorySize, GSMEM);
        cudaFuncSetAttribute(h_out_kernel, cudaFuncAttributeMaxDynamicSharedMemorySize, GSMEM);
        attr_done = 1;
    }

    cvt_all_kernel<<<7169, 256>>>(x, Wq, Wk, Wv, Wo, bq);
    h_qkv_kernel<<<dim3(24, SEQ / 128), 256, GSMEM>>>(bk, bv);
    flash_h_kernel<<<dim3(SEQ / 128, HEADS), dim3(128)>>>();
    h_out_kernel<<<dim3(HIDDEN / 128, SEQ / 128), 256, GSMEM>>>(bo, out);
}

// round 13
// speedup vs baseline: 1.2097x; 1.0423x over previous
#include <cuda_runtime.h>
#include <cuda_fp16.h>
#include <cstdint>

#define SEQ     2048
#define HIDDEN  2048
#define HEADS   32
#define GROUPS  8
#define HEAD_D  64
#define KV_DIM  512
#define QPG     4

__device__ __half g_xh[SEQ * HIDDEN];
__device__ __half g_Wqh[HIDDEN * HIDDEN];
__device__ __half g_Wkh[HIDDEN * KV_DIM];
__device__ __half g_Wvh[HIDDEN * KV_DIM];
__device__ __half g_Woh[HIDDEN * HIDDEN];
__device__ float  g_bqs[HIDDEN];
__device__ __half g_Qh[SEQ * HIDDEN];
__device__ __half g_Kh[SEQ * KV_DIM];
__device__ __half g_Vh[SEQ * KV_DIM];
__device__ __half g_Ah[SEQ * HIDDEN];

__device__ __forceinline__ uint32_t packh2(float lo, float hi) {
    __half2 h = __floats2half2_rn(lo, hi);
    return *(uint32_t*)&h;
}
__device__ __forceinline__ void mma_f16(float* c, const uint32_t* a, const uint32_t* b) {
    asm volatile(
        "mma.sync.aligned.m16n8k16.row.col.f32.f16.f16.f32 "
        "{%0,%1,%2,%3}, {%4,%5,%6,%7}, {%8,%9}, {%0,%1,%2,%3};\n"
        : "+f"(c[0]), "+f"(c[1]), "+f"(c[2]), "+f"(c[3])
        : "r"(a[0]), "r"(a[1]), "r"(a[2]), "r"(a[3]), "r"(b[0]), "r"(b[1]));
}
__device__ __forceinline__ void ldsm4(uint32_t& r0, uint32_t& r1, uint32_t& r2, uint32_t& r3, uint32_t a) {
    asm volatile("ldmatrix.sync.aligned.m8n8.x4.shared.b16 {%0,%1,%2,%3}, [%4];"
                 : "=r"(r0), "=r"(r1), "=r"(r2), "=r"(r3) : "r"(a));
}
__device__ __forceinline__ void ldsm4t(uint32_t& r0, uint32_t& r1, uint32_t& r2, uint32_t& r3, uint32_t a) {
    asm volatile("ldmatrix.sync.aligned.m8n8.x4.trans.shared.b16 {%0,%1,%2,%3}, [%4];"
                 : "=r"(r0), "=r"(r1), "=r"(r2), "=r"(r3) : "r"(a));
}
__device__ __forceinline__ void cpa16(uint32_t dst, const void* src) {
    asm volatile("cp.async.cg.shared.global [%0], [%1], 16;" :: "r"(dst), "l"(src));
}
__device__ __forceinline__ void cpcommit() { asm volatile("cp.async.commit_group;" ::: "memory"); }
template <int N> __device__ __forceinline__ void cpwait() {
    asm volatile("cp.async.wait_group %0;" :: "n"(N) : "memory");
}
__device__ __forceinline__ uint32_t h2exp2(uint32_t u) {
    uint32_t r;
    asm("ex2.approx.f16x2 %0, %1;" : "=r"(r) : "r"(u));
    return r;
}

// ---------------- fused precast: x, Wq*1/8, Wk, Wv, Wo, bq*1/8 (one launch)
__device__ __forceinline__ void cast8(const float* __restrict__ s, __half* __restrict__ d,
                                      int i, float sc) {
    float4 a = *(const float4*)&s[i], b = *(const float4*)&s[i + 4];
    *(uint4*)&d[i] = make_uint4(packh2(a.x * sc, a.y * sc), packh2(a.z * sc, a.w * sc),
                                packh2(b.x * sc, b.y * sc), packh2(b.z * sc, b.w * sc));
}
__global__ __launch_bounds__(256) void cvt_all_kernel(
    const float* __restrict__ x,  const float* __restrict__ Wq,
    const float* __restrict__ Wk, const float* __restrict__ Wv,
    const float* __restrict__ Wo, const float* __restrict__ bq)
{
    int c = blockIdx.x * 256 + threadIdx.x;
    if (c < 524288)        cast8(x,  g_xh,  c * 8, 1.f);
    else if (c < 1048576)  cast8(Wq, g_Wqh, (c - 524288) * 8, 0.125f);
    else if (c < 1179648)  cast8(Wk, g_Wkh, (c - 1048576) * 8, 1.f);
    else if (c < 1310720)  cast8(Wv, g_Wvh, (c - 1179648) * 8, 1.f);
    else if (c < 1835008)  cast8(Wo, g_Woh, (c - 1310720) * 8, 1.f);
    else {
        int i = (c - 1835008) * 8;
        float4 a = *(const float4*)&bq[i], b = *(const float4*)&bq[i + 4];
        *(float4*)&g_bqs[i]     = make_float4(a.x * .125f, a.y * .125f, a.z * .125f, a.w * .125f);
        *(float4*)&g_bqs[i + 4] = make_float4(b.x * .125f, b.y * .125f, b.z * .125f, b.w * .125f);
    }
}

// ---------------------------------------------------------------------------
// fp16 HMMA GEMM: 128x128 block tile, 8 warps of 64x32, BK=64, 3-stage
// cp.async multistage, 2 CTAs/SM. Stage: A [128][72] + B [64][136] halves
// (35840 B). Row strides 36/68 words (=4 mod 8, odd mult) -> ldmatrix
// conflict-free. Half the barriers of BK=32; 24 LDSM + 64 mma per iter.
// ---------------------------------------------------------------------------
#define STG     3
#define STG_B   35840                 // (128*72 + 64*136) halves * 2 bytes
#define GSMEM   (STG * STG_B)         // 107520 bytes

__device__ void hgemm16(const __half* __restrict__ A, const __half* __restrict__ B,
                        const float* __restrict__ bias, void* __restrict__ Cv,
                        int N, int K, int rb, int cb, int outHalf)
{
    extern __shared__ __half hs[];
    const int tid = threadIdx.x, warp = tid >> 5, lane = tid & 31;
    const int gid = lane >> 2, tg = lane & 3;
    const int mBase = (warp & 1) * 64, nBase = (warp >> 1) * 32;
    const uint32_t sbase = (uint32_t)__cvta_generic_to_shared(hs);

    const __half* Ab = A + (size_t)rb * 128 * K;
    const __half* Bb = B + (size_t)cb * 128;

    float acc[4][4][4];
#pragma unroll
    for (int i = 0; i < 4; i++)
#pragma unroll
        for (int j = 0; j < 4; j++)
#pragma unroll
            for (int r = 0; r < 4; r++) acc[i][j][r] = 0.f;

    const int T = K / 64;

    auto issue = [&](int t) {
        uint32_t as = sbase + (t % STG) * STG_B;
        uint32_t bs = as + 128 * 72 * 2;
#pragma unroll
        for (int p = 0; p < 4; p++) {   // A: 1024 chunks of 8 halves
            int s = tid + p * 256, row = s >> 3, c8 = (s & 7) * 8;
            cpa16(as + (row * 72 + c8) * 2, Ab + (size_t)row * K + t * 64 + c8);
        }
#pragma unroll
        for (int p = 0; p < 4; p++) {   // B: 1024 chunks
            int s = tid + p * 256, row = s >> 4, c8 = (s & 15) * 8;
            cpa16(bs + (row * 136 + c8) * 2, Bb + (size_t)(t * 64 + row) * N + c8);
        }
    };

#pragma unroll
    for (int s = 0; s < STG - 1; s++) { issue(s); cpcommit(); }

    for (int t = 0; t < T; t++) {
        cpwait<STG - 2>();           // stage t arrived
        __syncthreads();             // all warps past compute(t-1)
        if (t + STG - 1 < T) issue(t + STG - 1);
        cpcommit();
        const uint32_t as = sbase + (t % STG) * STG_B;
        const uint32_t bs = as + 128 * 72 * 2;
#pragma unroll
        for (int k0 = 0; k0 < 64; k0 += 16) {
            uint32_t af[4][4], bf[4][2];
#pragma unroll
            for (int mt = 0; mt < 4; mt++)
                ldsm4(af[mt][0], af[mt][1], af[mt][2], af[mt][3],
                      as + ((mBase + mt * 16 + (lane & 15)) * 72 + k0 + (lane >> 4) * 8) * 2);
#pragma unroll
            for (int np = 0; np < 2; np++)
                ldsm4t(bf[2 * np][0], bf[2 * np][1], bf[2 * np + 1][0], bf[2 * np + 1][1],
                       bs + ((k0 + (lane & 15)) * 136 + nBase + np * 16 + (lane >> 4) * 8) * 2);
#pragma unroll
            for (int mt = 0; mt < 4; mt++)
#pragma unroll
                for (int nt = 0; nt < 4; nt++)
                    mma_f16(acc[mt][nt], af[mt], bf[nt]);
        }
    }

#pragma unroll
    for (int mt = 0; mt < 4; mt++) {
#pragma unroll
        for (int nt = 0; nt < 4; nt++) {
            int row = rb * 128 + mBase + mt * 16 + gid;
            int col = cb * 128 + nBase + nt * 8 + tg * 2;
            float bx = bias[col], by = bias[col + 1];
            if (outHalf) {
                __half* C = (__half*)Cv;
                *(uint32_t*)&C[(size_t)row * N + col]       = packh2(acc[mt][nt][0] + bx, acc[mt][nt][1] + by);
                *(uint32_t*)&C[(size_t)(row + 8) * N + col] = packh2(acc[mt][nt][2] + bx, acc[mt][nt][3] + by);
            } else {
                float* C = (float*)Cv;
                *(float2*)&C[(size_t)row * N + col]       = make_float2(acc[mt][nt][0] + bx, acc[mt][nt][1] + by);
                *(float2*)&C[(size_t)(row + 8) * N + col] = make_float2(acc[mt][nt][2] + bx, acc[mt][nt][3] + by);
            }
        }
    }
}

__global__ __launch_bounds__(256, 2) void h_qkv_kernel(
    const float* __restrict__ bk, const float* __restrict__ bv)
{
    int bx = blockIdx.x;
    if (bx < 16)      hgemm16(g_xh, g_Wqh, g_bqs, g_Qh, HIDDEN, HIDDEN, blockIdx.y, bx, 1);
    else if (bx < 20) hgemm16(g_xh, g_Wkh, bk, g_Kh, KV_DIM, HIDDEN, blockIdx.y, bx - 16, 1);
    else              hgemm16(g_xh, g_Wvh, bv, g_Vh, KV_DIM, HIDDEN, blockIdx.y, bx - 20, 1);
}
__global__ __launch_bounds__(256, 2) void h_out_kernel(const float* __restrict__ bo, float* __restrict__ out)
{
    hgemm16(g_Ah, g_Woh, bo, out, HIDDEN, HIDDEN, blockIdx.y, blockIdx.x, 0);
}

// ---------------------------------------------------------------------------
// fp16 flash attention, double-buffered cp.async K/V, f16x2 exp2 softmax.
// grid=(SEQ/128, HEADS), block=128 (4 warps x 32 q-rows).  (unchanged)
// ---------------------------------------------------------------------------
__global__ __launch_bounds__(128) void flash_h_kernel()
{
    __shared__ __half Ks[2][64][72];
    __shared__ __half Vs[2][64][72];

    const int qblk = gridDim.x - 1 - blockIdx.x;
    const int h = blockIdx.y, g = h / QPG, q0 = qblk * 128;
    const int tid = threadIdx.x, warp = tid >> 5, lane = tid & 31;
    const int gid = lane >> 2, tg = lane & 3;
    const float L2E = 1.44269504f;

    uint32_t qa[2][4][4];
#pragma unroll
    for (int mt = 0; mt < 2; mt++) {
        const __half* QbA = g_Qh + (size_t)(q0 + warp * 32 + mt * 16 + gid) * HIDDEN + h * HEAD_D;
        const __half* QbB = QbA + 8 * HIDDEN;
#pragma unroll
        for (int ks = 0; ks < 4; ks++) {
            int c = ks * 16 + 2 * tg;
            qa[mt][ks][0] = *(const uint32_t*)&QbA[c];
            qa[mt][ks][1] = *(const uint32_t*)&QbB[c];
            qa[mt][ks][2] = *(const uint32_t*)&QbA[c + 8];
            qa[mt][ks][3] = *(const uint32_t*)&QbB[c + 8];
        }
    }

    float accO[2][8][4];
#pragma unroll
    for (int mt = 0; mt < 2; mt++)
#pragma unroll
        for (int nt = 0; nt < 8; nt++)
#pragma unroll
            for (int r = 0; r < 4; r++) accO[mt][nt][r] = 0.f;
    float mA[2] = {-1e30f, -1e30f}, mB[2] = {-1e30f, -1e30f};
    float lA[2] = {0.f, 0.f}, lB[2] = {0.f, 0.f};

    const int ntiles = 2 * qblk + 2;
    const int wmin = q0 + warp * 32, wmax = wmin + 31;

    auto issueKV = [&](int t) {
        int b = t & 1, j0 = t * 64;
#pragma unroll
        for (int i = 0; i < 4; i++) {
            int s = tid + i * 128, row = s >> 3, c8 = (s & 7) * 8;
            cpa16((uint32_t)__cvta_generic_to_shared(&Ks[b][row][c8]),
                  g_Kh + (size_t)(j0 + row) * KV_DIM + g * HEAD_D + c8);
        }
#pragma unroll
        for (int i = 0; i < 4; i++) {
            int s = tid + i * 128, row = s >> 3, c8 = (s & 7) * 8;
            cpa16((uint32_t)__cvta_generic_to_shared(&Vs[b][row][c8]),
                  g_Vh + (size_t)(j0 + row) * KV_DIM + g * HEAD_D + c8);
        }
    };

    issueKV(0);
    cpcommit();

    for (int t = 0; t < ntiles; t++) {
        const int j0 = t * 64, buf = t & 1;
        __syncthreads();
        if (t + 1 < ntiles) { issueKV(t + 1); cpcommit(); cpwait<1>(); }
        else                { cpwait<0>(); }
        __syncthreads();
        if (j0 > wmax) continue;

        float accS[2][8][4];
#pragma unroll
        for (int mt = 0; mt < 2; mt++)
#pragma unroll
            for (int nt = 0; nt < 8; nt++)
#pragma unroll
                for (int r = 0; r < 4; r++) accS[mt][nt][r] = 0.f;

#pragma unroll
        for (int ks = 0; ks < 4; ks++) {
#pragma unroll
            for (int np = 0; np < 4; np++) {
                uint32_t r0, r1, r2, r3;
                ldsm4(r0, r1, r2, r3,
                      (uint32_t)__cvta_generic_to_shared(
                          &Ks[buf][np * 16 + (lane & 15)][ks * 16 + (lane >> 4) * 8]));
                uint32_t b0[2] = {r0, r2}, b1[2] = {r1, r3};
                mma_f16(accS[0][2 * np],     qa[0][ks], b0);
                mma_f16(accS[1][2 * np],     qa[1][ks], b0);
                mma_f16(accS[0][2 * np + 1], qa[0][ks], b1);
                mma_f16(accS[1][2 * np + 1], qa[1][ks], b1);
            }
        }

        if (j0 + 63 > wmin) {
#pragma unroll
            for (int mt = 0; mt < 2; mt++) {
                int rA = wmin + mt * 16 + gid;
#pragma unroll
                for (int nt = 0; nt < 8; nt++) {
                    int k0 = j0 + nt * 8 + 2 * tg;
                    if (k0     > rA)     accS[mt][nt][0] = -1e30f;
                    if (k0 + 1 > rA)     accS[mt][nt][1] = -1e30f;
                    if (k0     > rA + 8) accS[mt][nt][2] = -1e30f;
                    if (k0 + 1 > rA + 8) accS[mt][nt][3] = -1e30f;
                }
            }
        }

        uint32_t p0[2][8], p1[2][8];
#pragma unroll
        for (int mt = 0; mt < 2; mt++) {
            float mx0 = -1e30f, mx1 = -1e30f;
#pragma unroll
            for (int nt = 0; nt < 8; nt++) {
                mx0 = fmaxf(mx0, fmaxf(accS[mt][nt][0], accS[mt][nt][1]));
                mx1 = fmaxf(mx1, fmaxf(accS[mt][nt][2], accS[mt][nt][3]));
            }
            mx0 = fmaxf(mx0, __shfl_xor_sync(0xffffffffu, mx0, 1));
            mx0 = fmaxf(mx0, __shfl_xor_sync(0xffffffffu, mx0, 2));
            mx1 = fmaxf(mx1, __shfl_xor_sync(0xffffffffu, mx1, 1));
            mx1 = fmaxf(mx1, __shfl_xor_sync(0xffffffffu, mx1, 2));
            float mn0 = fmaxf(mA[mt], mx0), mn1 = fmaxf(mB[mt], mx1);
            float sc0 = __expf(mA[mt] - mn0), sc1 = __expf(mB[mt] - mn1);
            float s0 = 0.f, s1 = 0.f;
#pragma unroll
            for (int nt = 0; nt < 8; nt++) {
                uint32_t u0 = h2exp2(packh2((accS[mt][nt][0] - mn0) * L2E,
                                            (accS[mt][nt][1] - mn0) * L2E));
                uint32_t u1 = h2exp2(packh2((accS[mt][nt][2] - mn1) * L2E,
                                            (accS[mt][nt][3] - mn1) * L2E));
                p0[mt][nt] = u0;
                p1[mt][nt] = u1;
                float2 f0 = __half22float2(*(__half2*)&u0);
                float2 f1 = __half22float2(*(__half2*)&u1);
                s0 += f0.x + f0.y;
                s1 += f1.x + f1.y;
            }
            s0 += __shfl_xor_sync(0xffffffffu, s0, 1);
            s0 += __shfl_xor_sync(0xffffffffu, s0, 2);
            s1 += __shfl_xor_sync(0xffffffffu, s1, 1);
            s1 += __shfl_xor_sync(0xffffffffu, s1, 2);
            lA[mt] = lA[mt] * sc0 + s0;
            lB[mt] = lB[mt] * sc1 + s1;
            mA[mt] = mn0; mB[mt] = mn1;
#pragma unroll
            for (int nt = 0; nt < 8; nt++) {
                accO[mt][nt][0] *= sc0; accO[mt][nt][1] *= sc0;
                accO[mt][nt][2] *= sc1; accO[mt][nt][3] *= sc1;
            }
        }

#pragma unroll
        for (int ks = 0; ks < 4; ks++) {
            uint32_t pa[2][4];
#pragma unroll
            for (int mt = 0; mt < 2; mt++) {
                pa[mt][0] = p0[mt][2 * ks];
                pa[mt][1] = p1[mt][2 * ks];
                pa[mt][2] = p0[mt][2 * ks + 1];
                pa[mt][3] = p1[mt][2 * ks + 1];
            }
#pragma unroll
            for (int np = 0; np < 4; np++) {
                uint32_t r0, r1, r2, r3;
                ldsm4t(r0, r1, r2, r3,
                       (uint32_t)__cvta_generic_to_shared(
                           &Vs[buf][ks * 16 + (lane & 15)][np * 16 + (lane >> 4) * 8]));
                uint32_t b0[2] = {r0, r1}, b1[2] = {r2, r3};
                mma_f16(accO[0][2 * np],     pa[0], b0);
                mma_f16(accO[1][2 * np],     pa[1], b0);
                mma_f16(accO[0][2 * np + 1], pa[0], b1);
                mma_f16(accO[1][2 * np + 1], pa[1], b1);
            }
        }
    }

#pragma unroll
    for (int mt = 0; mt < 2; mt++) {
        float inv0 = 1.f / lA[mt], inv1 = 1.f / lB[mt];
        __half* Ob = g_Ah + (size_t)(q0 + warp * 32 + mt * 16 + gid) * HIDDEN + h * HEAD_D;
#pragma unroll
        for (int nt = 0; nt < 8; nt++) {
            int c = nt * 8 + 2 * tg;
            *(uint32_t*)&Ob[c]              = packh2(accO[mt][nt][0] * inv0, accO[mt][nt][1] * inv0);
            *(uint32_t*)&Ob[8 * HIDDEN + c] = packh2(accO[mt][nt][2] * inv1, accO[mt][nt][3] * inv1);
        }
    }
}

// ---------------------------------------------------------------------------
extern "C" void kernel_launch(void* const* d_in, const int* in_sizes, int n_in,
                              void* d_out, int out_size)
{
    const float* x  = (const float*)d_in[0];
    const float* Wq = (const float*)d_in[2];
    const float* bq = (const float*)d_in[3];
    const float* Wk = (const float*)d_in[4];
    const float* bk = (const float*)d_in[5];
    const float* Wv = (const float*)d_in[6];
    const float* bv = (const float*)d_in[7];
    const float* Wo = (const float*)d_in[8];
    const float* bo = (const float*)d_in[9];
    float* out = (float*)d_out;

    static int attr_done = 0;
    if (!attr_done) {
        cudaFuncSetAttribute(h_qkv_kernel, cudaFuncAttributeMaxDynamicSharedMemorySize, GSMEM);
        cudaFuncSetAttribute(h_out_kernel, cudaFuncAttributeMaxDynamicSharedMemorySize, GSMEM);
        attr_done = 1;
    }

    cvt_all_kernel<<<7169, 256>>>(x, Wq, Wk, Wv, Wo, bq);
    h_qkv_kernel<<<dim3(24, SEQ / 128), 256, GSMEM>>>(bk, bv);
    flash_h_kernel<<<dim3(SEQ / 128, HEADS), dim3(128)>>>();
    h_out_kernel<<<dim3(HIDDEN / 128, SEQ / 128), 256, GSMEM>>>(bo, out);
}